// round 5
// baseline (speedup 1.0000x reference)
#include <cuda_runtime.h>
#include <cuda_bf16.h>

// ---------------------------------------------------------------------------
// RPN training loss (faithful port of the buggy reference), SINGLE KERNEL:
//   gt_idx[i] = argmax_j IoU(anchor_i, gt_j)   (first-max wins ties)
//   label = 1 if gt_idx >= 1, 0 if gt_idx == 0  (every anchor is pos or neg)
//   sel   = first min(num_pos,128) positives by anchor index, then negatives
//           by anchor index (spilling back into positives if negatives run out)
//   cls   = mean softmax-CE over 256 samples
//   reg   = mean over 256 of 2 * sum smoothL1(label * (pred - encode))
//
// Grid = 128 blocks x 256 threads. Every block computes argmax for its 256
// anchors in [0, 32768) + per-warp (32-anchor group) pos/neg counts, then
// threadfence+atomic-counter; the LAST block runs the tail:
//   scan 1024 group counts -> exclusive offsets (one Hillis-Steele pass),
//   warp-parallel scatter of the first-256 pos/neg anchors (no syncs between
//   iterations), then the 256-sample loss. If the 32768-anchor front lacks
//   128 pos or 128 neg (practically impossible), an exact whole-N fallback
//   runs inside the tail block.
// Argmax is division-free: best kept as a rational (bestI/bestU), update when
// inter*bestU > bestI*uni (strict '>' => first-max wins, matching jnp.argmax).
// ILP-2: independent even-j / odd-j chains merged at the end.
// ---------------------------------------------------------------------------

#define NMAX     (1 << 20)
#define GRID     128
#define THR      256
#define FRONT    (GRID * THR)        // 32768
#define NGRP     (FRONT / 32)        // 1024 groups of 32 anchors
#define GPT      (NGRP / THR)        // 4 groups per tail thread
#define SMG      512                 // gt boxes cached in smem (M <= SMG)
#define CAP      256

__device__ int g_gt_idx[NMAX];
__device__ int g_gp[NGRP];
__device__ int g_gn[NGRP];
__device__ unsigned int g_ctr;       // zero-init; reset by tail each call

// ---- division-free argmax, ILP-2 (even/odd chains) -----------------------
__device__ __forceinline__ int argmax_iou2(const float4 a,
                                           const float4* __restrict__ gtp,
                                           const float* __restrict__ areap,
                                           int M) {
    float areaA = (a.z - a.x) * (a.w - a.y);
    float bI0 = 0.0f, bU0 = 1.0f;   int b0 = 0;
    float bI1 = 0.0f, bU1 = 1.0f;   int b1 = 0;
    int j = 0;
    #pragma unroll 2
    for (; j + 1 < M; j += 2) {
        {
            float4 g = gtp[j];
            float w = fmaxf(fminf(a.z, g.z) - fmaxf(a.x, g.x), 0.0f);
            float h = fmaxf(fminf(a.w, g.w) - fmaxf(a.y, g.y), 0.0f);
            float inter = w * h;
            float uni = (areaA + areap[j]) - inter;
            bool u = inter * bU0 > bI0 * uni;
            bI0 = u ? inter : bI0;  bU0 = u ? uni : bU0;  b0 = u ? j : b0;
        }
        {
            float4 g = gtp[j + 1];
            float w = fmaxf(fminf(a.z, g.z) - fmaxf(a.x, g.x), 0.0f);
            float h = fmaxf(fminf(a.w, g.w) - fmaxf(a.y, g.y), 0.0f);
            float inter = w * h;
            float uni = (areaA + areap[j + 1]) - inter;
            bool u = inter * bU1 > bI1 * uni;
            bI1 = u ? inter : bI1;  bU1 = u ? uni : bU1;  b1 = u ? (j + 1) : b1;
        }
    }
    if (j < M) {  // M odd: last (even) index -> chain0
        float4 g = gtp[j];
        float w = fmaxf(fminf(a.z, g.z) - fmaxf(a.x, g.x), 0.0f);
        float h = fmaxf(fminf(a.w, g.w) - fmaxf(a.y, g.y), 0.0f);
        float inter = w * h;
        float uni = (areaA + areap[j]) - inter;
        bool u = inter * bU0 > bI0 * uni;
        bI0 = u ? inter : bI0;  bU0 = u ? uni : bU0;  b0 = u ? j : b0;
    }
    // merge: chain1 only on strict win (ties -> chain0, the even/first chain)
    return (bI1 * bU0 > bI0 * bU1) ? b1 : b0;
}

__device__ __forceinline__ int argmax_iou_global(const float4 a,
                                                 const float4* __restrict__ gt,
                                                 int M) {
    float areaA = (a.z - a.x) * (a.w - a.y);
    float bI = 0.0f, bU = 1.0f;
    int best = 0;
    for (int j = 0; j < M; ++j) {
        float4 g = __ldg(&gt[j]);
        float areaB = (g.z - g.x) * (g.w - g.y);
        float w = fmaxf(fminf(a.z, g.z) - fmaxf(a.x, g.x), 0.0f);
        float h = fmaxf(fminf(a.w, g.w) - fmaxf(a.y, g.y), 0.0f);
        float inter = w * h;
        float uni = (areaA + areaB) - inter;
        bool u = inter * bU > bI * uni;
        bI = u ? inter : bI;  bU = u ? uni : bU;  best = u ? j : best;
    }
    return best;
}

__global__ void __launch_bounds__(THR, 1)
k_fused(const float2* __restrict__ score,
        const float4* __restrict__ pred,
        const float4* __restrict__ anchors,
        const float4* __restrict__ gt,
        float* __restrict__ out,
        int N, int M) {
    __shared__ float4 sg[SMG];
    __shared__ float  sga[SMG];
    __shared__ int ssum_p[THR], ssum_n[THR];       // scan buffers
    __shared__ int s_po[NGRP], s_pn[NGRP];         // per-group excl offsets
    __shared__ int s_pos[CAP], s_neg[CAP];
    __shared__ int s_maxg, s_last;
    __shared__ int s_cntp, s_cntn;
    __shared__ int wps[8], wns[8];
    __shared__ float rc[THR], rr[THR];

    int t = threadIdx.x;
    int lane = t & 31;
    int warp = t >> 5;
    unsigned ltmask = (1u << lane) - 1u;

    // ---- gt cache ----
    int Ms = min(M, SMG);
    for (int j = t; j < Ms; j += THR) {
        float4 g = gt[j];
        sg[j]  = g;
        sga[j] = (g.z - g.x) * (g.w - g.y);
    }
    __syncthreads();

    // ---- phase 1: front argmax (this block's 256 anchors) ----
    int i = blockIdx.x * THR + t;
    int best = 0;
    bool valid = (i < N);
    if (valid) {
        best = (M <= SMG) ? argmax_iou2(anchors[i], sg, sga, M)
                          : argmax_iou_global(anchors[i], gt, M);
        g_gt_idx[i] = best;
    }
    unsigned bp = __ballot_sync(0xffffffffu, valid && best >= 1);
    unsigned bn = __ballot_sync(0xffffffffu, valid && best == 0);
    if (lane == 0) {
        int grp = blockIdx.x * 8 + warp;
        g_gp[grp] = __popc(bp);
        g_gn[grp] = __popc(bn);
    }

    // ---- last-block election (threadfence reduction pattern) ----
    __syncthreads();
    if (t == 0) {
        __threadfence();
        unsigned old = atomicAdd(&g_ctr, 1u);
        s_last = (old == (unsigned)(gridDim.x - 1));
    }
    __syncthreads();
    if (!s_last) return;

    // =================== TAIL (exactly one block) ===================
    if (t == 0) { s_maxg = 1; s_cntp = 0; s_cntn = 0; }
    s_pos[t] = 0;
    s_neg[t] = 0;

    // ---- scan 1024 group counts -> exclusive offsets + totals ----
    int cp[GPT], cn[GPT];
    int sump = 0, sumn = 0;
    #pragma unroll
    for (int k = 0; k < GPT; ++k) {
        cp[k] = g_gp[t * GPT + k];
        cn[k] = g_gn[t * GPT + k];
        sump += cp[k];
        sumn += cn[k];
    }
    ssum_p[t] = sump; ssum_n[t] = sumn;
    __syncthreads();
    #pragma unroll
    for (int off = 1; off < THR; off <<= 1) {
        int vp = (t >= off) ? ssum_p[t - off] : 0;
        int vn = (t >= off) ? ssum_n[t - off] : 0;
        __syncthreads();
        ssum_p[t] += vp; ssum_n[t] += vn;
        __syncthreads();
    }
    int num_pos = ssum_p[THR - 1];   // totals over front region
    int num_neg = ssum_n[THR - 1];
    {
        int rp = (t == 0) ? 0 : ssum_p[t - 1];
        int rn = (t == 0) ? 0 : ssum_n[t - 1];
        int need = -1;
        #pragma unroll
        for (int k = 0; k < GPT; ++k) {
            int g = t * GPT + k;
            s_po[g] = rp;
            s_pn[g] = rn;
            if (rp < CAP || rn < CAP) need = g;
            rp += cp[k];
            rn += cn[k];
        }
        if (need >= 0) atomicMax(&s_maxg, need + 1);
    }
    __syncthreads();

    bool suff = (num_pos >= 128) && (num_neg >= 128);

    if (suff) {
        // ---- parallel scatter: no syncs between group iterations ----
        int maxg = s_maxg;
        for (int g = warp; g < maxg; g += 8) {
            int po = s_po[g], no = s_pn[g];
            if (po >= CAP && no >= CAP) continue;
            int idx = g * 32 + lane;
            int gi = (idx < N) ? g_gt_idx[idx] : -1;
            int is_pos = (gi >= 1);
            int is_neg = (gi == 0);
            unsigned mp = __ballot_sync(0xffffffffu, is_pos);
            unsigned mn = __ballot_sync(0xffffffffu, is_neg);
            if (is_pos) {
                int r = po + __popc(mp & ltmask);
                if (r < CAP) s_pos[r] = idx;
            }
            if (is_neg) {
                int r = no + __popc(mn & ltmask);
                if (r < CAP) s_neg[r] = idx;
            }
        }
        __syncthreads();
    } else {
        // ---- exact fallback: finish argmax over [FRONT, N), then ordered
        //      chunk scan of the whole array (totals + lists exact) ----
        for (int ii = FRONT + t; ii < N; ii += THR) {
            int b = (M <= SMG) ? argmax_iou2(anchors[ii], sg, sga, M)
                               : argmax_iou_global(anchors[ii], gt, M);
            g_gt_idx[ii] = b;
        }
        __syncthreads();
        int gi0 = (t < N) ? g_gt_idx[t] : -1;
        for (int base = 0; base < N; base += THR) {
            int idx1 = base + THR + t;
            int gi1 = (idx1 < N) ? g_gt_idx[idx1] : -1;
            int cp0 = s_cntp, cn0 = s_cntn;
            int is_pos = (gi0 >= 1);
            int is_neg = (gi0 == 0);
            unsigned mp = __ballot_sync(0xffffffffu, is_pos);
            unsigned mn = __ballot_sync(0xffffffffu, is_neg);
            if (lane == 0) { wps[warp] = __popc(mp); wns[warp] = __popc(mn); }
            __syncthreads();
            int basep = 0, basen = 0;
            for (int w = 0; w < warp; ++w) { basep += wps[w]; basen += wns[w]; }
            if (is_pos) {
                int r = cp0 + basep + __popc(mp & ltmask);
                if (r < CAP) s_pos[r] = base + t;
            }
            if (is_neg) {
                int r = cn0 + basen + __popc(mn & ltmask);
                if (r < CAP) s_neg[r] = base + t;
            }
            if (t == 0) {
                int tp = 0, tn = 0;
                #pragma unroll
                for (int w = 0; w < 8; ++w) { tp += wps[w]; tn += wns[w]; }
                s_cntp = cp0 + tp;
                s_cntn = cn0 + tn;
            }
            __syncthreads();
            if (s_cntp >= CAP && s_cntn >= CAP) break;
            gi0 = gi1;
        }
        num_pos = s_cntp;
        num_neg = s_cntn;
    }

    // ---- mapping (counts >=128 give results identical to true totals:
    //      cur_pos = 128 and every j < 128 satisfies j < num_neg) ----
    int cur_pos = min(num_pos, 128);
    int a, label;
    if (t < cur_pos) {
        a = s_pos[t];
        label = 1;
    } else {
        int j = t - cur_pos;
        if (j < num_neg) {
            a = s_neg[min(j, CAP - 1)];
            label = 0;
        } else {
            // stable neg_order spills into positives in anchor-index order
            a = s_pos[min(j - num_neg, CAP - 1)];
            label = 1;
        }
    }

    // ---- classification: -log_softmax(score[a])[label] ----
    float2 s = score[a];
    float m = fmaxf(s.x, s.y);
    float lse = m + logf(expf(s.x - m) + expf(s.y - m));
    float cls = lse - (label ? s.y : s.x);

    // ---- regression: smooth-L1 on encoded target, zeroed for negatives ----
    float4 ab = anchors[a];
    int gi = g_gt_idx[a];
    float4 gb = (gi < Ms) ? sg[gi] : gt[gi];
    float aw = ab.z - ab.x, ah = ab.w - ab.y;
    float acx = ab.x + 0.5f * aw, acy = ab.y + 0.5f * ah;
    float gw = gb.z - gb.x, gh = gb.w - gb.y;
    float gcx = gb.x + 0.5f * gw, gcy = gb.y + 0.5f * gh;
    float t0 = (gcx - acx) / aw;
    float t1 = (gcy - acy) / ah;
    float t2 = logf(gw / aw);
    float t3 = logf(gh / ah);
    float4 p = pred[a];
    float fl = (float)label;
    float d0 = fl * (p.x - t0);
    float d1 = fl * (p.y - t1);
    float d2 = fl * (p.z - t2);
    float d3 = fl * (p.w - t3);
    float ad0 = fabsf(d0), ad1 = fabsf(d1), ad2 = fabsf(d2), ad3 = fabsf(d3);
    float s0 = (ad0 < 1.0f) ? 0.5f * d0 * d0 : ad0 - 0.5f;
    float s1 = (ad1 < 1.0f) ? 0.5f * d1 * d1 : ad1 - 0.5f;
    float s2 = (ad2 < 1.0f) ? 0.5f * d2 * d2 : ad2 - 0.5f;
    float s3 = (ad3 < 1.0f) ? 0.5f * d3 * d3 : ad3 - 0.5f;
    float reg = 2.0f * (s0 + s1 + s2 + s3);

    rc[t] = cls;
    rr[t] = reg;
    __syncthreads();
    for (int off = 128; off > 0; off >>= 1) {
        if (t < off) { rc[t] += rc[t + off]; rr[t] += rr[t + off]; }
        __syncthreads();
    }
    if (t == 0) {
        out[0] = rc[0] * (1.0f / 256.0f);   // CLS_W = 1.0
        out[1] = rr[0] * (1.0f / 256.0f);
        g_ctr = 0;                          // reset for next (graph) replay
    }
}

extern "C" void kernel_launch(void* const* d_in, const int* in_sizes, int n_in,
                              void* d_out, int out_size) {
    const float2* score   = (const float2*)d_in[0];   // [N,2]
    const float4* pred    = (const float4*)d_in[1];   // [N,4]
    const float4* anchors = (const float4*)d_in[2];   // [N,4]
    const float4* gt      = (const float4*)d_in[3];   // [M,4]
    float* out = (float*)d_out;

    int N = in_sizes[2] / 4;
    int M = in_sizes[3] / 4;

    k_fused<<<GRID, THR>>>(score, pred, anchors, gt, out, N, M);
}

// round 6
// speedup vs baseline: 1.1576x; 1.1576x over previous
#include <cuda_runtime.h>
#include <cuda_bf16.h>

// ---------------------------------------------------------------------------
// RPN training loss (faithful port of the buggy reference), SINGLE KERNEL:
//   gt_idx[i] = argmax_j IoU(anchor_i, gt_j)   (first-max wins ties)
//   label = 1 if gt_idx >= 1, 0 if gt_idx == 0  (every anchor is pos or neg)
//   sel   = first min(num_pos,128) positives by anchor index, then negatives
//           by anchor index (spilling back into positives if negatives run out)
//   cls   = mean softmax-CE over 256 samples
//   reg   = mean over 256 of 2 * sum smoothL1(label * (pred - encode))
//
// Grid = 64 blocks x 128 threads (1 warp/SMSP -> minimal cycles/SMSP).
// Front: argmax for anchors [0, 8192) -> g_gt_idx + per-32-anchor-group
// pos/neg ballot masks. Last block (threadfence+counter election) runs tail:
//   copy masks to smem, ONE-WARP shfl scan of 256 group popcounts ->
//   exclusive offsets + totals + maxg, smem-only scatter of the first-128
//   pos/neg anchors, 256-sample loss (2 samples/thread), shfl reduction.
// If the front lacks 128 pos or 128 neg (practically impossible), an exact
// whole-N fallback runs inside the tail block.
// Argmax is division-free: best kept as a rational (bestI/bestU), update when
// inter*bestU > bestI*uni (strict '>' => first-max wins, matching jnp.argmax).
// ---------------------------------------------------------------------------

#define NMAX     (1 << 20)
#define GRID     64
#define THR      128
#define FRONT    (GRID * THR)        // 8192
#define NGRP     (FRONT / 32)        // 256 groups of 32 anchors
#define SMG      512                 // gt boxes cached in smem (M <= SMG)
#define CAP      256

__device__ int g_gt_idx[NMAX];
__device__ unsigned g_pmask[NGRP];
__device__ unsigned g_nmask[NGRP];
__device__ unsigned int g_ctr;       // zero-init; reset by tail each call

// ---- division-free argmax, ILP-2 (even/odd chains) -----------------------
__device__ __forceinline__ int argmax_iou2(const float4 a,
                                           const float4* __restrict__ gtp,
                                           const float* __restrict__ areap,
                                           int M) {
    float areaA = (a.z - a.x) * (a.w - a.y);
    float bI0 = 0.0f, bU0 = 1.0f;   int b0 = 0;
    float bI1 = 0.0f, bU1 = 1.0f;   int b1 = 0;
    int j = 0;
    #pragma unroll 2
    for (; j + 1 < M; j += 2) {
        {
            float4 g = gtp[j];
            float w = fmaxf(fminf(a.z, g.z) - fmaxf(a.x, g.x), 0.0f);
            float h = fmaxf(fminf(a.w, g.w) - fmaxf(a.y, g.y), 0.0f);
            float inter = w * h;
            float uni = (areaA + areap[j]) - inter;
            bool u = inter * bU0 > bI0 * uni;
            bI0 = u ? inter : bI0;  bU0 = u ? uni : bU0;  b0 = u ? j : b0;
        }
        {
            float4 g = gtp[j + 1];
            float w = fmaxf(fminf(a.z, g.z) - fmaxf(a.x, g.x), 0.0f);
            float h = fmaxf(fminf(a.w, g.w) - fmaxf(a.y, g.y), 0.0f);
            float inter = w * h;
            float uni = (areaA + areap[j + 1]) - inter;
            bool u = inter * bU1 > bI1 * uni;
            bI1 = u ? inter : bI1;  bU1 = u ? uni : bU1;  b1 = u ? (j + 1) : b1;
        }
    }
    if (j < M) {  // M odd: last (even) index -> chain0
        float4 g = gtp[j];
        float w = fmaxf(fminf(a.z, g.z) - fmaxf(a.x, g.x), 0.0f);
        float h = fmaxf(fminf(a.w, g.w) - fmaxf(a.y, g.y), 0.0f);
        float inter = w * h;
        float uni = (areaA + areap[j]) - inter;
        bool u = inter * bU0 > bI0 * uni;
        bI0 = u ? inter : bI0;  bU0 = u ? uni : bU0;  b0 = u ? j : b0;
    }
    return (bI1 * bU0 > bI0 * bU1) ? b1 : b0;   // ties -> chain0 (even/first)
}

__device__ __forceinline__ int argmax_iou_global(const float4 a,
                                                 const float4* __restrict__ gt,
                                                 int M) {
    float areaA = (a.z - a.x) * (a.w - a.y);
    float bI = 0.0f, bU = 1.0f;
    int best = 0;
    for (int j = 0; j < M; ++j) {
        float4 g = __ldg(&gt[j]);
        float areaB = (g.z - g.x) * (g.w - g.y);
        float w = fmaxf(fminf(a.z, g.z) - fmaxf(a.x, g.x), 0.0f);
        float h = fmaxf(fminf(a.w, g.w) - fmaxf(a.y, g.y), 0.0f);
        float inter = w * h;
        float uni = (areaA + areaB) - inter;
        bool u = inter * bU > bI * uni;
        bI = u ? inter : bI;  bU = u ? uni : bU;  best = u ? j : best;
    }
    return best;
}

__global__ void __launch_bounds__(THR, 1)
k_fused(const float2* __restrict__ score,
        const float4* __restrict__ pred,
        const float4* __restrict__ anchors,
        const float4* __restrict__ gt,
        float* __restrict__ out,
        int N, int M) {
    __shared__ float4 sg[SMG];
    __shared__ float  sga[SMG];
    __shared__ unsigned s_pm[NGRP], s_nm[NGRP];
    __shared__ int s_po[NGRP], s_no[NGRP];
    __shared__ int s_pos[CAP], s_neg[CAP];
    __shared__ int s_last, s_maxg, s_nump, s_numn;
    __shared__ int s_cntp, s_cntn;
    __shared__ int wps[4], wns[4];
    __shared__ float s_rc[4], s_rr[4];

    int t = threadIdx.x;
    int lane = t & 31;
    int warp = t >> 5;
    unsigned ltmask = (1u << lane) - 1u;

    // ---- gt cache (all blocks need it for argmax) ----
    int Ms = min(M, SMG);
    for (int j = t; j < Ms; j += THR) {
        float4 g = gt[j];
        sg[j]  = g;
        sga[j] = (g.z - g.x) * (g.w - g.y);
    }
    __syncthreads();

    // ---- phase 1: front argmax (this block's 128 anchors) ----
    int i = blockIdx.x * THR + t;
    int best = 0;
    bool valid = (i < N);
    if (valid) {
        best = (M <= SMG) ? argmax_iou2(anchors[i], sg, sga, M)
                          : argmax_iou_global(anchors[i], gt, M);
        g_gt_idx[i] = best;
    }
    {
        unsigned bp = __ballot_sync(0xffffffffu, valid && best >= 1);
        unsigned bn = __ballot_sync(0xffffffffu, valid && best == 0);
        if (lane == 0) {
            int grp = blockIdx.x * 4 + warp;
            g_pmask[grp] = bp;
            g_nmask[grp] = bn;
        }
    }

    // ---- last-block election ----
    __syncthreads();
    if (t == 0) {
        __threadfence();
        unsigned old = atomicAdd(&g_ctr, 1u);
        s_last = (old == (unsigned)(gridDim.x - 1));
    }
    __syncthreads();
    if (!s_last) return;

    // =================== TAIL (exactly one block, 4 warps) ===================
    // bulk copy masks to smem (independent loads, latency overlapped)
    for (int k = t; k < NGRP; k += THR) {
        s_pm[k] = g_pmask[k];
        s_nm[k] = g_nmask[k];
    }
    s_pos[t] = 0;  s_pos[t + 128] = 0;
    s_neg[t] = 0;  s_neg[t + 128] = 0;
    if (t == 0) { s_cntp = 0; s_cntn = 0; }
    __syncthreads();

    // ---- one-warp shfl scan of 256 group popcounts ----
    if (warp == 0) {
        int cp[8], cn[8];
        int sump = 0, sumn = 0;
        #pragma unroll
        for (int k = 0; k < 8; ++k) {
            int g = lane * 8 + k;
            cp[k] = __popc(s_pm[g]);
            cn[k] = __popc(s_nm[g]);
            sump += cp[k];
            sumn += cn[k];
        }
        // inclusive shfl scan of per-lane sums
        int ip = sump, in_ = sumn;
        #pragma unroll
        for (int o = 1; o < 32; o <<= 1) {
            int vp = __shfl_up_sync(0xffffffffu, ip, o);
            int vn = __shfl_up_sync(0xffffffffu, in_, o);
            if (lane >= o) { ip += vp; in_ += vn; }
        }
        int rp = ip - sump;          // exclusive base for this lane
        int rn = in_ - sumn;
        int need = -1;
        #pragma unroll
        for (int k = 0; k < 8; ++k) {
            int g = lane * 8 + k;
            s_po[g] = rp;
            s_no[g] = rn;
            if (rp < 128 || rn < 128) need = g;
            rp += cp[k];
            rn += cn[k];
        }
        // warp max of (need + 1)
        int mg = need + 1;
        #pragma unroll
        for (int o = 16; o > 0; o >>= 1)
            mg = max(mg, __shfl_xor_sync(0xffffffffu, mg, o));
        if (lane == 31) {
            s_maxg = max(mg, 1);
            s_nump = ip;             // totals (lane 31 inclusive)
            s_numn = in_;
        }
    }
    __syncthreads();

    int num_pos = s_nump;
    int num_neg = s_numn;
    bool suff = (num_pos >= 128) && (num_neg >= 128);

    if (suff) {
        // ---- smem-only scatter of first-128 pos/neg anchors ----
        int maxg = s_maxg;
        for (int g = warp; g < maxg; g += 4) {
            int po = s_po[g], no = s_no[g];
            if (po >= 128 && no >= 128) continue;
            unsigned pm = s_pm[g], nm = s_nm[g];
            int idx = g * 32 + lane;
            if ((pm >> lane) & 1u) {
                int r = po + __popc(pm & ltmask);
                if (r < 128) s_pos[r] = idx;
            }
            if ((nm >> lane) & 1u) {
                int r = no + __popc(nm & ltmask);
                if (r < 128) s_neg[r] = idx;
            }
        }
        __syncthreads();
    } else {
        // ---- exact fallback: finish argmax over [FRONT, N), then ordered
        //      chunk scan of the whole array (totals + lists exact) ----
        for (int ii = FRONT + t; ii < N; ii += THR) {
            int b = (M <= SMG) ? argmax_iou2(anchors[ii], sg, sga, M)
                               : argmax_iou_global(anchors[ii], gt, M);
            g_gt_idx[ii] = b;
        }
        __syncthreads();
        int gi0 = (t < N) ? g_gt_idx[t] : -1;
        for (int base = 0; base < N; base += THR) {
            int idx1 = base + THR + t;
            int gi1 = (idx1 < N) ? g_gt_idx[idx1] : -1;
            int cp0 = s_cntp, cn0 = s_cntn;
            int is_pos = (gi0 >= 1);
            int is_neg = (gi0 == 0);
            unsigned mp = __ballot_sync(0xffffffffu, is_pos);
            unsigned mn = __ballot_sync(0xffffffffu, is_neg);
            if (lane == 0) { wps[warp] = __popc(mp); wns[warp] = __popc(mn); }
            __syncthreads();
            int basep = 0, basen = 0;
            for (int w = 0; w < warp; ++w) { basep += wps[w]; basen += wns[w]; }
            if (is_pos) {
                int r = cp0 + basep + __popc(mp & ltmask);
                if (r < CAP) s_pos[r] = base + t;
            }
            if (is_neg) {
                int r = cn0 + basen + __popc(mn & ltmask);
                if (r < CAP) s_neg[r] = base + t;
            }
            if (t == 0) {
                int tp = 0, tn = 0;
                #pragma unroll
                for (int w = 0; w < 4; ++w) { tp += wps[w]; tn += wns[w]; }
                s_cntp = cp0 + tp;
                s_cntn = cn0 + tn;
            }
            __syncthreads();
            if (s_cntp >= CAP && s_cntn >= CAP) break;
            gi0 = gi1;
        }
        num_pos = s_cntp;
        num_neg = s_cntn;
    }

    // ---- 256-sample loss, 2 samples per thread ----
    int cur_pos = min(num_pos, 128);
    float csum = 0.0f, rsum = 0.0f;

    #pragma unroll
    for (int ss = 0; ss < 2; ++ss) {
        int sid = t + ss * 128;
        int a, label;
        if (sid < cur_pos) {
            a = s_pos[sid];
            label = 1;
        } else {
            int j = sid - cur_pos;
            if (j < num_neg) {
                a = s_neg[min(j, CAP - 1)];
                label = 0;
            } else {
                // stable neg_order spills into positives in anchor-index order
                a = s_pos[min(j - num_neg, CAP - 1)];
                label = 1;
            }
        }

        // classification: -log_softmax(score[a])[label]
        float2 s = score[a];
        float m = fmaxf(s.x, s.y);
        float lse = m + logf(expf(s.x - m) + expf(s.y - m));
        csum += lse - (label ? s.y : s.x);

        // regression: smooth-L1 on encoded target, zeroed for negatives
        float4 ab = anchors[a];
        int gi = g_gt_idx[a];
        float4 gb = (gi < Ms) ? sg[gi] : gt[gi];
        float aw = ab.z - ab.x, ah = ab.w - ab.y;
        float acx = ab.x + 0.5f * aw, acy = ab.y + 0.5f * ah;
        float gw = gb.z - gb.x, gh = gb.w - gb.y;
        float gcx = gb.x + 0.5f * gw, gcy = gb.y + 0.5f * gh;
        float t0 = (gcx - acx) / aw;
        float t1 = (gcy - acy) / ah;
        float t2 = logf(gw / aw);
        float t3 = logf(gh / ah);
        float4 p = pred[a];
        float fl = (float)label;
        float d0 = fl * (p.x - t0);
        float d1 = fl * (p.y - t1);
        float d2 = fl * (p.z - t2);
        float d3 = fl * (p.w - t3);
        float ad0 = fabsf(d0), ad1 = fabsf(d1), ad2 = fabsf(d2), ad3 = fabsf(d3);
        float s0 = (ad0 < 1.0f) ? 0.5f * d0 * d0 : ad0 - 0.5f;
        float s1 = (ad1 < 1.0f) ? 0.5f * d1 * d1 : ad1 - 0.5f;
        float s2 = (ad2 < 1.0f) ? 0.5f * d2 * d2 : ad2 - 0.5f;
        float s3 = (ad3 < 1.0f) ? 0.5f * d3 * d3 : ad3 - 0.5f;
        rsum += 2.0f * (s0 + s1 + s2 + s3);
    }

    // ---- shfl reduction over 128 threads ----
    #pragma unroll
    for (int o = 16; o > 0; o >>= 1) {
        csum += __shfl_down_sync(0xffffffffu, csum, o);
        rsum += __shfl_down_sync(0xffffffffu, rsum, o);
    }
    if (lane == 0) { s_rc[warp] = csum; s_rr[warp] = rsum; }
    __syncthreads();
    if (t == 0) {
        float c = s_rc[0] + s_rc[1] + s_rc[2] + s_rc[3];
        float r = s_rr[0] + s_rr[1] + s_rr[2] + s_rr[3];
        out[0] = c * (1.0f / 256.0f);   // CLS_W = 1.0
        out[1] = r * (1.0f / 256.0f);
        g_ctr = 0;                      // reset for next (graph) replay
    }
}

extern "C" void kernel_launch(void* const* d_in, const int* in_sizes, int n_in,
                              void* d_out, int out_size) {
    const float2* score   = (const float2*)d_in[0];   // [N,2]
    const float4* pred    = (const float4*)d_in[1];   // [N,4]
    const float4* anchors = (const float4*)d_in[2];   // [N,4]
    const float4* gt      = (const float4*)d_in[3];   // [M,4]
    float* out = (float*)d_out;

    int N = in_sizes[2] / 4;
    int M = in_sizes[3] / 4;

    k_fused<<<GRID, THR>>>(score, pred, anchors, gt, out, N, M);
}

// round 7
// speedup vs baseline: 1.3663x; 1.1802x over previous
#include <cuda_runtime.h>
#include <cuda_bf16.h>

// ---------------------------------------------------------------------------
// RPN training loss (faithful port of the buggy reference), SINGLE KERNEL:
//   gt_idx[i] = argmax_j IoU(anchor_i, gt_j)   (first-max wins ties)
//   label = 1 if gt_idx >= 1, 0 if gt_idx == 0  (every anchor is pos or neg)
//   sel   = first min(num_pos,128) positives by anchor index, then negatives
//           by anchor index (spilling back into positives if negatives run out)
//   cls   = mean softmax-CE over 256 samples
//   reg   = mean over 256 of 2 * sum smoothL1(label * (pred - encode))
//
// Grid = 128 blocks x 256 threads. Front: anchors [0, 8192), FOUR threads per
// anchor (chain sub handles j = sub, sub+4, ...), merged with 2 shfl_xor steps
// using the division-free rational compare + exact min-index tie-break
// (equality -> smaller j wins => global first-max, matching jnp.argmax).
// Lane layout lane = sub*8 + a_local puts each warp's 8 anchor results in
// lanes 0-7 -> one ballot gives an 8-anchor pos/neg mask byte.
// Last block (threadfence+counter election) runs the tail: assemble 32-anchor
// masks, one-warp shfl scan -> offsets/totals, smem-only scatter of first-128
// pos/neg anchors, 256-sample loss, shfl reduction. Exact whole-N fallback if
// the front lacks 128 pos or 128 neg (practically impossible).
// ---------------------------------------------------------------------------

#define NMAX     (1 << 20)
#define GRID     128
#define THR      256
#define APB      64                  // anchors per block (4 threads/anchor)
#define FRONT    (GRID * APB)        // 8192
#define NGRP     (FRONT / 32)        // 256 groups of 32 anchors
#define NG8      (FRONT / 8)         // 1024 groups of 8 anchors
#define SMG      512                 // gt boxes cached in smem (M <= SMG)
#define CAP      256

__device__ int g_gt_idx[NMAX];
__device__ __align__(16) unsigned g_pm8[NG8];
__device__ __align__(16) unsigned g_nm8[NG8];
__device__ unsigned int g_ctr;       // zero-init; reset by tail each call

// ---- full-M division-free argmax (fallback paths) ------------------------
__device__ __forceinline__ int argmax_iou_full(const float4 a,
                                               const float4* __restrict__ gtp,
                                               const float* __restrict__ areap,
                                               int M) {
    float areaA = (a.z - a.x) * (a.w - a.y);
    float bI = 0.0f, bU = 1.0f;
    int best = 0;
    #pragma unroll 4
    for (int j = 0; j < M; ++j) {
        float4 g = gtp[j];
        float w = fmaxf(fminf(a.z, g.z) - fmaxf(a.x, g.x), 0.0f);
        float h = fmaxf(fminf(a.w, g.w) - fmaxf(a.y, g.y), 0.0f);
        float inter = w * h;
        float uni = (areaA + areap[j]) - inter;
        bool u = inter * bU > bI * uni;
        bI = u ? inter : bI;  bU = u ? uni : bU;  best = u ? j : best;
    }
    return best;
}

__device__ __forceinline__ int argmax_iou_global(const float4 a,
                                                 const float4* __restrict__ gt,
                                                 int M) {
    float areaA = (a.z - a.x) * (a.w - a.y);
    float bI = 0.0f, bU = 1.0f;
    int best = 0;
    for (int j = 0; j < M; ++j) {
        float4 g = __ldg(&gt[j]);
        float areaB = (g.z - g.x) * (g.w - g.y);
        float w = fmaxf(fminf(a.z, g.z) - fmaxf(a.x, g.x), 0.0f);
        float h = fmaxf(fminf(a.w, g.w) - fmaxf(a.y, g.y), 0.0f);
        float inter = w * h;
        float uni = (areaA + areaB) - inter;
        bool u = inter * bU > bI * uni;
        bI = u ? inter : bI;  bU = u ? uni : bU;  best = u ? j : best;
    }
    return best;
}

__global__ void __launch_bounds__(THR, 1)
k_fused(const float2* __restrict__ score,
        const float4* __restrict__ pred,
        const float4* __restrict__ anchors,
        const float4* __restrict__ gt,
        float* __restrict__ out,
        int N, int M) {
    __shared__ float4 sg[SMG];
    __shared__ float  sga[SMG];
    __shared__ unsigned s_pm[NGRP], s_nm[NGRP];
    __shared__ int s_po[NGRP], s_no[NGRP];
    __shared__ int s_pos[CAP], s_neg[CAP];
    __shared__ int s_last, s_maxg, s_nump, s_numn;
    __shared__ int s_cntp, s_cntn;
    __shared__ int wps[8], wns[8];
    __shared__ float s_rc[8], s_rr[8];

    int t = threadIdx.x;
    int lane = t & 31;
    int warp = t >> 5;
    unsigned ltmask = (1u << lane) - 1u;

    // ---- gt cache (all blocks: argmax; tail: loss encode) ----
    int Ms = min(M, SMG);
    for (int j = t; j < Ms; j += THR) {
        float4 g = gt[j];
        sg[j]  = g;
        sga[j] = (g.z - g.x) * (g.w - g.y);
    }
    __syncthreads();

    // ---- phase 1: front argmax, 4 threads per anchor ----
    // lane = sub*8 + a_local : warp covers 8 anchors, chain sub does j%4==sub
    int sub = lane >> 3;
    int al  = lane & 7;
    int i = blockIdx.x * APB + warp * 8 + al;
    bool valid = (i < N);
    int bb;
    if (M <= SMG) {
        float4 a = valid ? anchors[i] : make_float4(0.f, 0.f, 1.f, 1.f);
        float areaA = (a.z - a.x) * (a.w - a.y);
        float bI = 0.0f, bU = 1.0f;
        bb = sub;                       // chain's first index (argmax(0s)=first)
        for (int j = sub; j < M; j += 4) {
            float4 g = sg[j];
            float w = fmaxf(fminf(a.z, g.z) - fmaxf(a.x, g.x), 0.0f);
            float h = fmaxf(fminf(a.w, g.w) - fmaxf(a.y, g.y), 0.0f);
            float inter = w * h;
            float uni = (areaA + sga[j]) - inter;
            bool u = inter * bU > bI * uni;   // strict > : first max kept
            bI = u ? inter : bI;  bU = u ? uni : bU;  bb = u ? j : bb;
        }
        // merge the 4 chains (xor 8, xor 16); exact tie-break -> min index
        #pragma unroll
        for (int o = 8; o <= 16; o <<= 1) {
            float oI = __shfl_xor_sync(0xffffffffu, bI, o);
            float oU = __shfl_xor_sync(0xffffffffu, bU, o);
            int   ob = __shfl_xor_sync(0xffffffffu, bb, o);
            float l = oI * bU, r = bI * oU;
            bool take = (l > r) || (l == r && ob < bb);
            bI = take ? oI : bI;  bU = take ? oU : bU;  bb = take ? ob : bb;
        }
    } else {
        // huge-M fallback: per-thread full argmax (lanes 0-7 do real work)
        bb = (valid && sub == 0) ? argmax_iou_global(anchors[i], gt, M) : 0;
    }
    if (valid && sub == 0) g_gt_idx[i] = bb;
    {
        unsigned bp = __ballot_sync(0xffffffffu, sub == 0 && valid && bb >= 1);
        unsigned bn = __ballot_sync(0xffffffffu, sub == 0 && valid && bb == 0);
        if (lane == 0) {
            int g8 = blockIdx.x * 8 + warp;
            g_pm8[g8] = bp & 0xffu;
            g_nm8[g8] = bn & 0xffu;
        }
    }

    // ---- last-block election ----
    __syncthreads();
    if (t == 0) {
        __threadfence();
        unsigned old = atomicAdd(&g_ctr, 1u);
        s_last = (old == (unsigned)(gridDim.x - 1));
    }
    __syncthreads();
    if (!s_last) return;

    // =================== TAIL (exactly one block, 8 warps) ===================
    // assemble 32-anchor masks (one uint4 per group)
    {
        const uint4* pm4 = (const uint4*)g_pm8;
        const uint4* nm4 = (const uint4*)g_nm8;
        for (int g = t; g < NGRP; g += THR) {
            uint4 vp = pm4[g];
            uint4 vn = nm4[g];
            s_pm[g] = vp.x | (vp.y << 8) | (vp.z << 16) | (vp.w << 24);
            s_nm[g] = vn.x | (vn.y << 8) | (vn.z << 16) | (vn.w << 24);
        }
    }
    s_pos[t] = 0;
    s_neg[t] = 0;
    if (t == 0) { s_cntp = 0; s_cntn = 0; }
    __syncthreads();

    // ---- one-warp shfl scan of 256 group popcounts ----
    if (warp == 0) {
        int cp[8], cn[8];
        int sump = 0, sumn = 0;
        #pragma unroll
        for (int k = 0; k < 8; ++k) {
            int g = lane * 8 + k;
            cp[k] = __popc(s_pm[g]);
            cn[k] = __popc(s_nm[g]);
            sump += cp[k];
            sumn += cn[k];
        }
        int ip = sump, in_ = sumn;
        #pragma unroll
        for (int o = 1; o < 32; o <<= 1) {
            int vp = __shfl_up_sync(0xffffffffu, ip, o);
            int vn = __shfl_up_sync(0xffffffffu, in_, o);
            if (lane >= o) { ip += vp; in_ += vn; }
        }
        int rp = ip - sump;
        int rn = in_ - sumn;
        int need = -1;
        #pragma unroll
        for (int k = 0; k < 8; ++k) {
            int g = lane * 8 + k;
            s_po[g] = rp;
            s_no[g] = rn;
            if (rp < 128 || rn < 128) need = g;
            rp += cp[k];
            rn += cn[k];
        }
        int mg = need + 1;
        #pragma unroll
        for (int o = 16; o > 0; o >>= 1)
            mg = max(mg, __shfl_xor_sync(0xffffffffu, mg, o));
        if (lane == 31) {
            s_maxg = max(mg, 1);
            s_nump = ip;
            s_numn = in_;
        }
    }
    __syncthreads();

    int num_pos = s_nump;
    int num_neg = s_numn;
    bool suff = (num_pos >= 128) && (num_neg >= 128);

    if (suff) {
        // ---- smem-only scatter of first-128 pos/neg anchors ----
        int maxg = s_maxg;
        for (int g = warp; g < maxg; g += 8) {
            int po = s_po[g], no = s_no[g];
            if (po >= 128 && no >= 128) continue;
            unsigned pm = s_pm[g], nm = s_nm[g];
            int idx = g * 32 + lane;
            if ((pm >> lane) & 1u) {
                int r = po + __popc(pm & ltmask);
                if (r < 128) s_pos[r] = idx;
            }
            if ((nm >> lane) & 1u) {
                int r = no + __popc(nm & ltmask);
                if (r < 128) s_neg[r] = idx;
            }
        }
        __syncthreads();
    } else {
        // ---- exact fallback: finish argmax over [FRONT, N), then ordered
        //      chunk scan of the whole array (totals + lists exact) ----
        for (int ii = FRONT + t; ii < N; ii += THR) {
            int b = (M <= SMG) ? argmax_iou_full(anchors[ii], sg, sga, M)
                               : argmax_iou_global(anchors[ii], gt, M);
            g_gt_idx[ii] = b;
        }
        __syncthreads();
        int gi0 = (t < N) ? g_gt_idx[t] : -1;
        for (int base = 0; base < N; base += THR) {
            int idx1 = base + THR + t;
            int gi1 = (idx1 < N) ? g_gt_idx[idx1] : -1;
            int cp0 = s_cntp, cn0 = s_cntn;
            int is_pos = (gi0 >= 1);
            int is_neg = (gi0 == 0);
            unsigned mp = __ballot_sync(0xffffffffu, is_pos);
            unsigned mn = __ballot_sync(0xffffffffu, is_neg);
            if (lane == 0) { wps[warp] = __popc(mp); wns[warp] = __popc(mn); }
            __syncthreads();
            int basep = 0, basen = 0;
            for (int w = 0; w < warp; ++w) { basep += wps[w]; basen += wns[w]; }
            if (is_pos) {
                int r = cp0 + basep + __popc(mp & ltmask);
                if (r < CAP) s_pos[r] = base + t;
            }
            if (is_neg) {
                int r = cn0 + basen + __popc(mn & ltmask);
                if (r < CAP) s_neg[r] = base + t;
            }
            if (t == 0) {
                int tp = 0, tn = 0;
                #pragma unroll
                for (int w = 0; w < 8; ++w) { tp += wps[w]; tn += wns[w]; }
                s_cntp = cp0 + tp;
                s_cntn = cn0 + tn;
            }
            __syncthreads();
            if (s_cntp >= CAP && s_cntn >= CAP) break;
            gi0 = gi1;
        }
        num_pos = s_cntp;
        num_neg = s_cntn;
    }

    // ---- 256-sample loss, 1 sample per thread ----
    int cur_pos = min(num_pos, 128);
    int a, label;
    if (t < cur_pos) {
        a = s_pos[t];
        label = 1;
    } else {
        int j = t - cur_pos;
        if (j < num_neg) {
            a = s_neg[min(j, CAP - 1)];
            label = 0;
        } else {
            // stable neg_order spills into positives in anchor-index order
            a = s_pos[min(j - num_neg, CAP - 1)];
            label = 1;
        }
    }

    // classification: -log_softmax(score[a])[label]
    float2 s = score[a];
    float m = fmaxf(s.x, s.y);
    float lse = m + logf(expf(s.x - m) + expf(s.y - m));
    float csum = lse - (label ? s.y : s.x);

    // regression: smooth-L1 on encoded target, zeroed for negatives
    float4 ab = anchors[a];
    int gi = g_gt_idx[a];
    float4 gb = (gi < Ms) ? sg[gi] : gt[gi];
    float aw = ab.z - ab.x, ah = ab.w - ab.y;
    float acx = ab.x + 0.5f * aw, acy = ab.y + 0.5f * ah;
    float gw = gb.z - gb.x, gh = gb.w - gb.y;
    float gcx = gb.x + 0.5f * gw, gcy = gb.y + 0.5f * gh;
    float t0 = (gcx - acx) / aw;
    float t1 = (gcy - acy) / ah;
    float t2 = logf(gw / aw);
    float t3 = logf(gh / ah);
    float4 p = pred[a];
    float fl = (float)label;
    float d0 = fl * (p.x - t0);
    float d1 = fl * (p.y - t1);
    float d2 = fl * (p.z - t2);
    float d3 = fl * (p.w - t3);
    float ad0 = fabsf(d0), ad1 = fabsf(d1), ad2 = fabsf(d2), ad3 = fabsf(d3);
    float s0 = (ad0 < 1.0f) ? 0.5f * d0 * d0 : ad0 - 0.5f;
    float s1 = (ad1 < 1.0f) ? 0.5f * d1 * d1 : ad1 - 0.5f;
    float s2 = (ad2 < 1.0f) ? 0.5f * d2 * d2 : ad2 - 0.5f;
    float s3 = (ad3 < 1.0f) ? 0.5f * d3 * d3 : ad3 - 0.5f;
    float rsum = 2.0f * (s0 + s1 + s2 + s3);

    // ---- reduction: shfl within warps + 8 partials ----
    #pragma unroll
    for (int o = 16; o > 0; o >>= 1) {
        csum += __shfl_down_sync(0xffffffffu, csum, o);
        rsum += __shfl_down_sync(0xffffffffu, rsum, o);
    }
    if (lane == 0) { s_rc[warp] = csum; s_rr[warp] = rsum; }
    __syncthreads();
    if (t == 0) {
        float c = 0.0f, r = 0.0f;
        #pragma unroll
        for (int w = 0; w < 8; ++w) { c += s_rc[w]; r += s_rr[w]; }
        out[0] = c * (1.0f / 256.0f);   // CLS_W = 1.0
        out[1] = r * (1.0f / 256.0f);
        g_ctr = 0;                      // reset for next (graph) replay
    }
}

extern "C" void kernel_launch(void* const* d_in, const int* in_sizes, int n_in,
                              void* d_out, int out_size) {
    const float2* score   = (const float2*)d_in[0];   // [N,2]
    const float4* pred    = (const float4*)d_in[1];   // [N,4]
    const float4* anchors = (const float4*)d_in[2];   // [N,4]
    const float4* gt      = (const float4*)d_in[3];   // [M,4]
    float* out = (float*)d_out;

    int N = in_sizes[2] / 4;
    int M = in_sizes[3] / 4;

    k_fused<<<GRID, THR>>>(score, pred, anchors, gt, out, N, M);
}

// round 8
// speedup vs baseline: 1.3988x; 1.0238x over previous
#include <cuda_runtime.h>
#include <cuda_bf16.h>

// ---------------------------------------------------------------------------
// RPN training loss (faithful port of the buggy reference), SINGLE KERNEL:
//   gt_idx[i] = argmax_j IoU(anchor_i, gt_j)   (first-max wins ties)
//   label = 1 if gt_idx >= 1, 0 if gt_idx == 0  (every anchor is pos or neg)
//   sel   = first min(num_pos,128) positives by anchor index, then negatives
//           by anchor index (spilling back into positives if negatives run out)
//   cls   = mean softmax-CE over 256 samples
//   reg   = mean over 256 of 2 * sum smoothL1(label * (pred - encode))
//
// Grid = 48 blocks x 256 threads. Front: anchors [0, 3072), FOUR threads per
// anchor (chain sub handles j = sub, sub+4, ...) reading gt straight from
// global (no smem staging barrier), merged with 2 shfl_xor steps using the
// division-free rational compare + exact min-index tie-break (equality ->
// smaller j wins => global first-max, matching jnp.argmax). Lane layout
// lane = sub*8 + a_local puts each warp's 8 anchor results in lanes 0-7 ->
// one ballot gives an 8-anchor pos/neg mask byte.
// Last block (fence+counter election) runs the tail: assemble 32-anchor
// masks, one-warp shfl scan -> offsets/totals, smem-only scatter of first-128
// pos/neg anchors, 256-sample loss, shfl reduction. Exact whole-N fallback if
// the front lacks 128 pos or 128 neg (practically impossible).
// ---------------------------------------------------------------------------

#define NMAX     (1 << 20)
#define GRID     48
#define THR      256
#define APB      64                  // anchors per block (4 threads/anchor)
#define FRONT    (GRID * APB)        // 3072
#define NGRP     (FRONT / 32)        // 96 groups of 32 anchors
#define NG8      (FRONT / 8)         // 384 groups of 8 anchors
#define CAP      256

__device__ int g_gt_idx[NMAX];
__device__ __align__(16) unsigned g_pm8[NG8];
__device__ __align__(16) unsigned g_nm8[NG8];
__device__ unsigned int g_ctr;       // zero-init; reset by tail each call

// ---- full-M division-free argmax from global (fallback path) -------------
__device__ __forceinline__ int argmax_iou_global(const float4 a,
                                                 const float4* __restrict__ gt,
                                                 int M) {
    float areaA = (a.z - a.x) * (a.w - a.y);
    float bI = 0.0f, bU = 1.0f;
    int best = 0;
    #pragma unroll 4
    for (int j = 0; j < M; ++j) {
        float4 g = __ldg(&gt[j]);
        float areaB = (g.z - g.x) * (g.w - g.y);
        float w = fmaxf(fminf(a.z, g.z) - fmaxf(a.x, g.x), 0.0f);
        float h = fmaxf(fminf(a.w, g.w) - fmaxf(a.y, g.y), 0.0f);
        float inter = w * h;
        float uni = (areaA + areaB) - inter;
        bool u = inter * bU > bI * uni;
        bI = u ? inter : bI;  bU = u ? uni : bU;  best = u ? j : best;
    }
    return best;
}

__global__ void __launch_bounds__(THR, 1)
k_fused(const float2* __restrict__ score,
        const float4* __restrict__ pred,
        const float4* __restrict__ anchors,
        const float4* __restrict__ gt,
        float* __restrict__ out,
        int N, int M) {
    __shared__ unsigned s_pm[NGRP], s_nm[NGRP];
    __shared__ int s_po[NGRP], s_no[NGRP];
    __shared__ int s_pos[CAP], s_neg[CAP];
    __shared__ int s_last, s_maxg, s_nump, s_numn;
    __shared__ int s_cntp, s_cntn;
    __shared__ int wps[8], wns[8];
    __shared__ float s_rc[8], s_rr[8];

    int t = threadIdx.x;
    int lane = t & 31;
    int warp = t >> 5;
    unsigned ltmask = (1u << lane) - 1u;

    // ---- phase 1: front argmax, 4 threads per anchor, gt straight from L1/L2
    // lane = sub*8 + a_local : warp covers 8 anchors, chain sub does j%4==sub
    int sub = lane >> 3;
    int al  = lane & 7;
    int i = blockIdx.x * APB + warp * 8 + al;
    bool valid = (i < N);
    int bb;
    {
        float4 a = valid ? __ldg(&anchors[i]) : make_float4(0.f, 0.f, 1.f, 1.f);
        float areaA = (a.z - a.x) * (a.w - a.y);
        float bI = 0.0f, bU = 1.0f;
        bb = sub;                       // chain's first index (argmax(0s)=first)
        #pragma unroll 4
        for (int j = sub; j < M; j += 4) {
            float4 g = __ldg(&gt[j]);
            float areaB = (g.z - g.x) * (g.w - g.y);
            float w = fmaxf(fminf(a.z, g.z) - fmaxf(a.x, g.x), 0.0f);
            float h = fmaxf(fminf(a.w, g.w) - fmaxf(a.y, g.y), 0.0f);
            float inter = w * h;
            float uni = (areaA + areaB) - inter;
            bool u = inter * bU > bI * uni;   // strict > : first max kept
            bI = u ? inter : bI;  bU = u ? uni : bU;  bb = u ? j : bb;
        }
        // merge the 4 chains (xor 8, xor 16); exact tie-break -> min index
        #pragma unroll
        for (int o = 8; o <= 16; o <<= 1) {
            float oI = __shfl_xor_sync(0xffffffffu, bI, o);
            float oU = __shfl_xor_sync(0xffffffffu, bU, o);
            int   ob = __shfl_xor_sync(0xffffffffu, bb, o);
            float l = oI * bU, r = bI * oU;
            bool take = (l > r) || (l == r && ob < bb);
            bI = take ? oI : bI;  bU = take ? oU : bU;  bb = take ? ob : bb;
        }
    }
    if (valid && sub == 0) g_gt_idx[i] = bb;
    {
        unsigned bp = __ballot_sync(0xffffffffu, sub == 0 && valid && bb >= 1);
        unsigned bn = __ballot_sync(0xffffffffu, sub == 0 && valid && bb == 0);
        if (lane == 0) {
            int g8 = blockIdx.x * 8 + warp;
            g_pm8[g8] = bp & 0xffu;
            g_nm8[g8] = bn & 0xffu;
        }
    }

    // ---- last-block election (fence by every thread orders all writers) ----
    __threadfence();
    __syncthreads();
    if (t == 0) {
        unsigned old = atomicAdd(&g_ctr, 1u);
        s_last = (old == (unsigned)(gridDim.x - 1));
    }
    __syncthreads();
    if (!s_last) return;
    __threadfence();   // acquire side: all front writes now visible

    // =================== TAIL (exactly one block, 8 warps) ===================
    // assemble 32-anchor masks (one uint4 per group)
    {
        const uint4* pm4 = (const uint4*)g_pm8;
        const uint4* nm4 = (const uint4*)g_nm8;
        for (int g = t; g < NGRP; g += THR) {
            uint4 vp = pm4[g];
            uint4 vn = nm4[g];
            s_pm[g] = vp.x | (vp.y << 8) | (vp.z << 16) | (vp.w << 24);
            s_nm[g] = vn.x | (vn.y << 8) | (vn.z << 16) | (vn.w << 24);
        }
    }
    s_pos[t] = 0;
    s_neg[t] = 0;
    if (t == 0) { s_cntp = 0; s_cntn = 0; }
    __syncthreads();

    // ---- one-warp shfl scan of 96 group popcounts ----
    if (warp == 0) {
        int cp[3], cn[3];
        int sump = 0, sumn = 0;
        #pragma unroll
        for (int k = 0; k < 3; ++k) {
            int g = lane * 3 + k;
            cp[k] = __popc(s_pm[g]);
            cn[k] = __popc(s_nm[g]);
            sump += cp[k];
            sumn += cn[k];
        }
        int ip = sump, in_ = sumn;
        #pragma unroll
        for (int o = 1; o < 32; o <<= 1) {
            int vp = __shfl_up_sync(0xffffffffu, ip, o);
            int vn = __shfl_up_sync(0xffffffffu, in_, o);
            if (lane >= o) { ip += vp; in_ += vn; }
        }
        int rp = ip - sump;
        int rn = in_ - sumn;
        int need = -1;
        #pragma unroll
        for (int k = 0; k < 3; ++k) {
            int g = lane * 3 + k;
            s_po[g] = rp;
            s_no[g] = rn;
            if (rp < 128 || rn < 128) need = g;
            rp += cp[k];
            rn += cn[k];
        }
        int mg = need + 1;
        #pragma unroll
        for (int o = 16; o > 0; o >>= 1)
            mg = max(mg, __shfl_xor_sync(0xffffffffu, mg, o));
        if (lane == 31) {
            s_maxg = max(mg, 1);
            s_nump = ip;
            s_numn = in_;
        }
    }
    __syncthreads();

    int num_pos = s_nump;
    int num_neg = s_numn;
    bool suff = (num_pos >= 128) && (num_neg >= 128);

    if (suff) {
        // ---- smem-only scatter of first-128 pos/neg anchors ----
        int maxg = s_maxg;
        for (int g = warp; g < maxg; g += 8) {
            int po = s_po[g], no = s_no[g];
            if (po >= 128 && no >= 128) continue;
            unsigned pm = s_pm[g], nm = s_nm[g];
            int idx = g * 32 + lane;
            if ((pm >> lane) & 1u) {
                int r = po + __popc(pm & ltmask);
                if (r < 128) s_pos[r] = idx;
            }
            if ((nm >> lane) & 1u) {
                int r = no + __popc(nm & ltmask);
                if (r < 128) s_neg[r] = idx;
            }
        }
        __syncthreads();
    } else {
        // ---- exact fallback: finish argmax over [FRONT, N), then ordered
        //      chunk scan of the whole array (totals + lists exact) ----
        for (int ii = FRONT + t; ii < N; ii += THR) {
            g_gt_idx[ii] = argmax_iou_global(__ldg(&anchors[ii]), gt, M);
        }
        __syncthreads();
        int gi0 = (t < N) ? g_gt_idx[t] : -1;
        for (int base = 0; base < N; base += THR) {
            int idx1 = base + THR + t;
            int gi1 = (idx1 < N) ? g_gt_idx[idx1] : -1;
            int cp0 = s_cntp, cn0 = s_cntn;
            int is_pos = (gi0 >= 1);
            int is_neg = (gi0 == 0);
            unsigned mp = __ballot_sync(0xffffffffu, is_pos);
            unsigned mn = __ballot_sync(0xffffffffu, is_neg);
            if (lane == 0) { wps[warp] = __popc(mp); wns[warp] = __popc(mn); }
            __syncthreads();
            int basep = 0, basen = 0;
            for (int w = 0; w < warp; ++w) { basep += wps[w]; basen += wns[w]; }
            if (is_pos) {
                int r = cp0 + basep + __popc(mp & ltmask);
                if (r < CAP) s_pos[r] = base + t;
            }
            if (is_neg) {
                int r = cn0 + basen + __popc(mn & ltmask);
                if (r < CAP) s_neg[r] = base + t;
            }
            if (t == 0) {
                int tp = 0, tn = 0;
                #pragma unroll
                for (int w = 0; w < 8; ++w) { tp += wps[w]; tn += wns[w]; }
                s_cntp = cp0 + tp;
                s_cntn = cn0 + tn;
            }
            __syncthreads();
            if (s_cntp >= CAP && s_cntn >= CAP) break;
            gi0 = gi1;
        }
        num_pos = s_cntp;
        num_neg = s_cntn;
    }

    // ---- 256-sample loss, 1 sample per thread ----
    int cur_pos = min(num_pos, 128);
    int a, label;
    if (t < cur_pos) {
        a = s_pos[t];
        label = 1;
    } else {
        int j = t - cur_pos;
        if (j < num_neg) {
            a = s_neg[min(j, CAP - 1)];
            label = 0;
        } else {
            // stable neg_order spills into positives in anchor-index order
            a = s_pos[min(j - num_neg, CAP - 1)];
            label = 1;
        }
    }

    // classification: -log_softmax(score[a])[label]
    float2 s = __ldg(&score[a]);
    float m = fmaxf(s.x, s.y);
    float lse = m + logf(expf(s.x - m) + expf(s.y - m));
    float csum = lse - (label ? s.y : s.x);

    // regression: smooth-L1 on encoded target, zeroed for negatives
    float4 ab = __ldg(&anchors[a]);
    int gi = g_gt_idx[a];
    float4 gb = __ldg(&gt[gi]);
    float aw = ab.z - ab.x, ah = ab.w - ab.y;
    float acx = ab.x + 0.5f * aw, acy = ab.y + 0.5f * ah;
    float gw = gb.z - gb.x, gh = gb.w - gb.y;
    float gcx = gb.x + 0.5f * gw, gcy = gb.y + 0.5f * gh;
    float t0 = (gcx - acx) / aw;
    float t1 = (gcy - acy) / ah;
    float t2 = logf(gw / aw);
    float t3 = logf(gh / ah);
    float4 p = __ldg(&pred[a]);
    float fl = (float)label;
    float d0 = fl * (p.x - t0);
    float d1 = fl * (p.y - t1);
    float d2 = fl * (p.z - t2);
    float d3 = fl * (p.w - t3);
    float ad0 = fabsf(d0), ad1 = fabsf(d1), ad2 = fabsf(d2), ad3 = fabsf(d3);
    float s0 = (ad0 < 1.0f) ? 0.5f * d0 * d0 : ad0 - 0.5f;
    float s1 = (ad1 < 1.0f) ? 0.5f * d1 * d1 : ad1 - 0.5f;
    float s2 = (ad2 < 1.0f) ? 0.5f * d2 * d2 : ad2 - 0.5f;
    float s3 = (ad3 < 1.0f) ? 0.5f * d3 * d3 : ad3 - 0.5f;
    float rsum = 2.0f * (s0 + s1 + s2 + s3);

    // ---- reduction: shfl within warps + 8 partials ----
    #pragma unroll
    for (int o = 16; o > 0; o >>= 1) {
        csum += __shfl_down_sync(0xffffffffu, csum, o);
        rsum += __shfl_down_sync(0xffffffffu, rsum, o);
    }
    if (lane == 0) { s_rc[warp] = csum; s_rr[warp] = rsum; }
    __syncthreads();
    if (t == 0) {
        float c = 0.0f, r = 0.0f;
        #pragma unroll
        for (int w = 0; w < 8; ++w) { c += s_rc[w]; r += s_rr[w]; }
        out[0] = c * (1.0f / 256.0f);   // CLS_W = 1.0
        out[1] = r * (1.0f / 256.0f);
        g_ctr = 0;                      // reset for next (graph) replay
    }
}

extern "C" void kernel_launch(void* const* d_in, const int* in_sizes, int n_in,
                              void* d_out, int out_size) {
    const float2* score   = (const float2*)d_in[0];   // [N,2]
    const float4* pred    = (const float4*)d_in[1];   // [N,4]
    const float4* anchors = (const float4*)d_in[2];   // [N,4]
    const float4* gt      = (const float4*)d_in[3];   // [M,4]
    float* out = (float*)d_out;

    int N = in_sizes[2] / 4;
    int M = in_sizes[3] / 4;

    k_fused<<<GRID, THR>>>(score, pred, anchors, gt, out, N, M);
}